// round 12
// baseline (speedup 1.0000x reference)
#include <cuda_runtime.h>
#include <cuda_bf16.h>
#include <cstdint>

// GCN: 3 layers, N=50000, E=600000, D=128.
// Out layout: [total | x0 | x1 | x2 | x3], each n*D f32.
// HMMA split-precision GEMM; CSR aggregate; single persistent prep kernel.

#define DD 128
#define MAXN 50016
#define MAXE 600000
#define LDT 136
#define PREP_BLOCKS 512

// Scratch (device globals; no allocation allowed)
__device__ float g_y[(size_t)MAXN * DD];
__device__ int   g_src[MAXE];
__device__ int   g_dst[MAXE];
__device__ int   g_off[MAXE];
__device__ int   g_csrc[MAXE];
__device__ float g_cw[MAXE];       // = dinv[src]  (dinv[dst] factored out)
__device__ float g_dinv[MAXN];
__device__ int   g_deg[MAXN];
__device__ int   g_rowstart[MAXN];
__device__ int   g_bsum[128];
__device__ int   g_is64;
__device__ int   g_bar_count = 0;
__device__ volatile int g_bar_gen = 0;

// ---------------------------------------------------------------------------
__device__ __forceinline__ void grid_bar() {
    __threadfence();
    __syncthreads();
    if (threadIdx.x == 0) {
        int gen = g_bar_gen;
        if (atomicAdd(&g_bar_count, 1) == (int)gridDim.x - 1) {
            atomicExch(&g_bar_count, 0);
            __threadfence();
            g_bar_gen = gen + 1;
        } else {
            while (g_bar_gen == gen) { }
        }
    }
    __syncthreads();
}

__device__ __forceinline__ uint32_t smem_u32(const void* p) {
    uint32_t a;
    asm("{ .reg .u64 t; cvta.to.shared.u64 t, %1; cvt.u32.u64 %0, t; }" : "=r"(a) : "l"(p));
    return a;
}
__device__ __forceinline__ void ldm_x4(uint32_t* r, uint32_t addr) {
    asm volatile("ldmatrix.sync.aligned.m8n8.x4.shared.b16 {%0,%1,%2,%3}, [%4];"
                 : "=r"(r[0]), "=r"(r[1]), "=r"(r[2]), "=r"(r[3]) : "r"(addr));
}
__device__ __forceinline__ void ldm_x4_t(uint32_t* r, uint32_t addr) {
    asm volatile("ldmatrix.sync.aligned.m8n8.x4.trans.shared.b16 {%0,%1,%2,%3}, [%4];"
                 : "=r"(r[0]), "=r"(r[1]), "=r"(r[2]), "=r"(r[3]) : "r"(addr));
}
__device__ __forceinline__ void mma_bf16(float* c, const uint32_t* a, const uint32_t* b) {
    asm volatile(
        "mma.sync.aligned.m16n8k16.row.col.f32.bf16.bf16.f32 "
        "{%0,%1,%2,%3}, {%4,%5,%6,%7}, {%8,%9}, {%0,%1,%2,%3};"
        : "+f"(c[0]), "+f"(c[1]), "+f"(c[2]), "+f"(c[3])
        : "r"(a[0]), "r"(a[1]), "r"(a[2]), "r"(a[3]), "r"(b[0]), "r"(b[1]));
}
__device__ __forceinline__ uint32_t bfbits(float v) {
    return (uint32_t)__bfloat16_as_ushort(__float2bfloat16(v));
}
__device__ __forceinline__ float bfval(uint32_t b) {
    return __bfloat162float(__ushort_as_bfloat16((unsigned short)b));
}

#define T_ELE (128 * LDT)
#define GEMM_SMEM (4 * T_ELE * 2)

// ---------------------------------------------------------------------------
// GEMM: g_y = x @ W via HMMA split precision (verified R4/R11, unchanged).
__global__ __launch_bounds__(256) void k_gemm_mma(const float* __restrict__ x,
                                                  const float* __restrict__ W, int n) {
    extern __shared__ __align__(16) char smem[];
    __nv_bfloat16* AH = (__nv_bfloat16*)smem;
    __nv_bfloat16* AL = AH + T_ELE;
    __nv_bfloat16* BH = AL + T_ELE;
    __nv_bfloat16* BL = BH + T_ELE;

    int tid = threadIdx.x;
    int wid = tid >> 5, lane = tid & 31;
    int row0 = blockIdx.x * 128;

#pragma unroll
    for (int i = 0; i < 16; i++) {
        int idx = tid + i * 256;
        int r = idx >> 5, f = idx & 31;
        int grow = row0 + r;
        float4 v = make_float4(0.f, 0.f, 0.f, 0.f);
        if (grow < n) v = *(const float4*)(x + (size_t)grow * DD + f * 4);
        uint32_t hx = bfbits(v.x), hy = bfbits(v.y), hz = bfbits(v.z), hw = bfbits(v.w);
        uint2 hh = make_uint2((hy << 16) | hx, (hw << 16) | hz);
        uint2 ll = make_uint2((bfbits(v.y - bfval(hy)) << 16) | bfbits(v.x - bfval(hx)),
                              (bfbits(v.w - bfval(hw)) << 16) | bfbits(v.z - bfval(hz)));
        *(uint2*)(AH + r * LDT + f * 4) = hh;
        *(uint2*)(AL + r * LDT + f * 4) = ll;
    }
#pragma unroll
    for (int i = 0; i < 16; i++) {
        int idx = tid + i * 256;
        int r = idx >> 5, f = idx & 31;
        float4 v = *(const float4*)(W + (size_t)r * DD + f * 4);
        uint32_t hx = bfbits(v.x), hy = bfbits(v.y), hz = bfbits(v.z), hw = bfbits(v.w);
        uint2 hh = make_uint2((hy << 16) | hx, (hw << 16) | hz);
        uint2 ll = make_uint2((bfbits(v.y - bfval(hy)) << 16) | bfbits(v.x - bfval(hx)),
                              (bfbits(v.w - bfval(hw)) << 16) | bfbits(v.z - bfval(hz)));
        *(uint2*)(BH + r * LDT + f * 4) = hh;
        *(uint2*)(BL + r * LDT + f * 4) = ll;
    }
    __syncthreads();

    int m0 = wid * 16;
    uint32_t a_off_h = smem_u32(AH + (m0 + (lane & 15)) * LDT + (lane >> 4) * 8);
    uint32_t a_off_l = a_off_h + (uint32_t)(T_ELE * 2);

    float acc[16][4];
#pragma unroll
    for (int j = 0; j < 16; j++)
#pragma unroll
        for (int q = 0; q < 4; q++) acc[j][q] = 0.0f;

#pragma unroll
    for (int k = 0; k < 8; k++) {
        uint32_t ah[4], al[4];
        ldm_x4(ah, a_off_h + k * 32);
        ldm_x4(al, a_off_l + k * 32);
        uint32_t b_base = smem_u32(BH + (k * 16 + (lane & 15)) * LDT + (lane >> 4) * 8);
#pragma unroll
        for (int j2 = 0; j2 < 8; j2++) {
            uint32_t bh[4], bl[4];
            ldm_x4_t(bh, b_base + j2 * 32);
            ldm_x4_t(bl, b_base + j2 * 32 + (uint32_t)(T_ELE * 2));
            mma_bf16(acc[2 * j2],     ah, bh);
            mma_bf16(acc[2 * j2],     ah, bl);
            mma_bf16(acc[2 * j2],     al, bh);
            mma_bf16(acc[2 * j2 + 1], ah, bh + 2);
            mma_bf16(acc[2 * j2 + 1], ah, bl + 2);
            mma_bf16(acc[2 * j2 + 1], al, bh + 2);
        }
    }

    int r_lo = row0 + m0 + (lane >> 2);
    int r_hi = r_lo + 8;
    int cbase = (lane & 3) * 2;
#pragma unroll
    for (int j = 0; j < 16; j++) {
        int col = j * 8 + cbase;
        if (r_lo < n) *(float2*)(g_y + (size_t)r_lo * DD + col) = make_float2(acc[j][0], acc[j][1]);
        if (r_hi < n) *(float2*)(g_y + (size_t)r_hi * DD + col) = make_float2(acc[j][2], acc[j][3]);
    }
}

// ---------------------------------------------------------------------------
// Persistent prep: zero+detect -> convert/deg/x0copy -> bucket scan ->
// prefix add -> fill.  All blocks co-resident; software grid barriers.
__global__ __launch_bounds__(256) void k_prep_all(const void* __restrict__ raw, int E, int n,
                                                  const float* __restrict__ emb,
                                                  float* __restrict__ x0) {
    int tid = threadIdx.x;
    int gid = blockIdx.x * 256 + tid;
    int gsz = gridDim.x * 256;

    // P0: zero deg + detect dtype
    for (int i = gid; i < n; i += gsz) g_deg[i] = 0;
    if (gid == 0) {
        const unsigned int* r = (const unsigned int*)raw;
        g_is64 = (r[1] == 0u && r[3] == 0u && r[5] == 0u &&
                  r[7] == 0u && r[9] == 0u && r[11] == 0u) ? 1 : 0;
    }
    grid_bar();

    // P1: convert edges + degree count (+slot offset); x0 copy
    if (g_is64) {
        const long long* p = (const long long*)raw;
        for (int e = gid; e < E; e += gsz) {
            int s = (int)p[e], d = (int)p[e + E];
            g_src[e] = s; g_dst[e] = d;
            g_off[e] = atomicAdd(&g_deg[d], 1);
        }
    } else {
        const int* p = (const int*)raw;
        for (int e = gid; e < E; e += gsz) {
            int s = p[e], d = p[e + E];
            g_src[e] = s; g_dst[e] = d;
            g_off[e] = atomicAdd(&g_deg[d], 1);
        }
    }
    {
        int nd4 = n * (DD / 4);
        for (int i = gid; i < nd4; i += gsz)
            ((float4*)x0)[i] = ((const float4*)emb)[i];
    }
    grid_bar();

    // P2: per-bucket (512 nodes) exclusive scan + dinv.  Blocks 0..nb-1.
    int nb = (n + 511) >> 9;
    __shared__ int wsum[8];
    if ((int)blockIdx.x < nb) {
        int base = (int)blockIdx.x << 9;
        int i0 = base + 2 * tid, i1 = i0 + 1;
        int v0 = (i0 < n) ? g_deg[i0] : 0;
        int v1 = (i1 < n) ? g_deg[i1] : 0;
        if (i0 < n) g_dinv[i0] = rsqrtf((float)(v0 + 1));
        if (i1 < n) g_dinv[i1] = rsqrtf((float)(v1 + 1));
        int s = v0 + v1;
        int lane = tid & 31, wid = tid >> 5;
        int incl = s;
#pragma unroll
        for (int o = 1; o < 32; o <<= 1) {
            int u = __shfl_up_sync(0xFFFFFFFFu, incl, o);
            if (lane >= o) incl += u;
        }
        if (lane == 31) wsum[wid] = incl;
        __syncthreads();
        if (wid == 0) {
            int ws = (lane < 8) ? wsum[lane] : 0;
#pragma unroll
            for (int o = 1; o < 8; o <<= 1) {
                int u = __shfl_up_sync(0xFFFFFFFFu, ws, o);
                if (lane >= o) ws += u;
            }
            if (lane < 8) wsum[lane] = ws;
        }
        __syncthreads();
        int woff = (wid == 0) ? 0 : wsum[wid - 1];
        incl += woff;
        int excl = incl - s;
        if (i0 < n) g_rowstart[i0] = excl;
        if (i1 < n) g_rowstart[i1] = excl + v0;
        if (tid == 255) g_bsum[blockIdx.x] = incl;
    }
    grid_bar();

    // P3: add bucket prefix to rowstart (per-block smem scan of g_bsum)
    __shared__ int s_pre[128];
    if (tid < 128) s_pre[tid] = (tid < nb) ? g_bsum[tid] : 0;
    __syncthreads();
#pragma unroll
    for (int o = 1; o < 128; o <<= 1) {
        int v = (tid < 128 && tid >= o) ? s_pre[tid - o] : 0;
        __syncthreads();
        if (tid < 128) s_pre[tid] += v;
        __syncthreads();
    }
    for (int i = gid; i < n; i += gsz) {
        int bk = i >> 9;
        g_rowstart[i] += (bk ? s_pre[bk - 1] : 0);
    }
    grid_bar();

    // P4: fill CSR
    for (int e = gid; e < E; e += gsz) {
        int s = g_src[e], d = g_dst[e];
        int pos = g_rowstart[d] + g_off[e];
        g_csrc[pos] = s;
        g_cw[pos]   = g_dinv[s];
    }
}

// ---------------------------------------------------------------------------
// Aggregate (verified R11, unchanged): xout = bias + dinv^2*y + dinv*sum.
__global__ __launch_bounds__(256) void k_aggregate(const float* __restrict__ bias,
                                                   float* __restrict__ xout,
                                                   float* __restrict__ total,
                                                   const float* __restrict__ xbase,
                                                   int n) {
    int t = blockIdx.x * blockDim.x + threadIdx.x;
    int node = t >> 5, lane = t & 31;
    if (node >= n) return;

    const float4* y4 = (const float4*)g_y;
    float ex = 0.f, ey = 0.f, ez = 0.f, ew = 0.f;

    int st  = g_rowstart[node];
    int cnt = g_deg[node];
    int k = 0;
    for (; k + 3 < cnt; k += 4) {
        int   s0 = g_csrc[st + k],     s1 = g_csrc[st + k + 1];
        int   s2 = g_csrc[st + k + 2], s3 = g_csrc[st + k + 3];
        float w0 = g_cw[st + k],       w1 = g_cw[st + k + 1];
        float w2 = g_cw[st + k + 2],   w3 = g_cw[st + k + 3];
        float4 v0 = __ldcg(y4 + (size_t)s0 * 32 + lane);
        float4 v1 = __ldcg(y4 + (size_t)s1 * 32 + lane);
        float4 v2 = __ldcg(y4 + (size_t)s2 * 32 + lane);
        float4 v3 = __ldcg(y4 + (size_t)s3 * 32 + lane);
        ex = fmaf(v0.x, w0, ex); ey = fmaf(v0.y, w0, ey);
        ez = fmaf(v0.z, w0, ez); ew = fmaf(v0.w, w0, ew);
        ex = fmaf(v1.x, w1, ex); ey = fmaf(v1.y, w1, ey);
        ez = fmaf(v1.z, w1, ez); ew = fmaf(v1.w, w1, ew);
        ex = fmaf(v2.x, w2, ex); ey = fmaf(v2.y, w2, ey);
        ez = fmaf(v2.z, w2, ez); ew = fmaf(v2.w, w2, ew);
        ex = fmaf(v3.x, w3, ex); ey = fmaf(v3.y, w3, ey);
        ez = fmaf(v3.z, w3, ez); ew = fmaf(v3.w, w3, ew);
    }
    for (; k < cnt; k++) {
        int   s0 = g_csrc[st + k];
        float w0 = g_cw[st + k];
        float4 v0 = __ldcg(y4 + (size_t)s0 * 32 + lane);
        ex = fmaf(v0.x, w0, ex); ey = fmaf(v0.y, w0, ey);
        ez = fmaf(v0.z, w0, ez); ew = fmaf(v0.w, w0, ew);
    }

    float s  = g_dinv[node];
    float s2 = s * s;
    float4 bb = ((const float4*)bias)[lane];
    float4 vs = y4[(size_t)node * 32 + lane];
    float ax = bb.x + fmaf(vs.x, s2, s * ex);
    float ay = bb.y + fmaf(vs.y, s2, s * ey);
    float az = bb.z + fmaf(vs.z, s2, s * ez);
    float aw = bb.w + fmaf(vs.w, s2, s * ew);

    size_t idx = (size_t)node * 32 + lane;
    ((float4*)xout)[idx] = make_float4(ax, ay, az, aw);

    if (total) {
        size_t nd4 = (size_t)n * 32;
        const float4* xb = (const float4*)xbase;
        float4 a = xb[idx], b2 = xb[nd4 + idx], c = xb[2 * nd4 + idx];
        ((float4*)total)[idx] = make_float4(a.x + b2.x + c.x + ax,
                                            a.y + b2.y + c.y + ay,
                                            a.z + b2.z + c.z + az,
                                            a.w + b2.w + c.w + aw);
    }
}

// ---------------------------------------------------------------------------
extern "C" void kernel_launch(void* const* d_in, const int* in_sizes, int n_in,
                              void* d_out, int out_size) {
    const float* item_emb = (const float*)d_in[0];
    const float* weights  = (const float*)d_in[1];
    const float* biases   = (const float*)d_in[2];
    const void*  edge_raw = d_in[3];

    int n = out_size / (5 * DD);
    int E = in_sizes[3] / 2;
    int emb_off = in_sizes[0] - n * DD;
    float* out = (float*)d_out;

    static bool attr_set = false;
    if (!attr_set) {
        cudaFuncSetAttribute(k_gemm_mma, cudaFuncAttributeMaxDynamicSharedMemorySize, GEMM_SMEM);
        attr_set = true;
    }

    const int TB = 256;
    int nb_gemm = (n + 127) / 128;
    long long agg_threads = (long long)n * 32;
    int nb_agg = (int)((agg_threads + TB - 1) / TB);

    const float* x0_src = item_emb + emb_off;
    float* x0_dst = out + (size_t)n * DD;

    // GEMM_0 reads item_emb directly (x0 == item_emb[-n:]) — issue first.
    k_gemm_mma<<<nb_gemm, 256, GEMM_SMEM>>>(x0_src, weights, n);

    // Entire CSR build + x0 copy: one persistent kernel.
    k_prep_all<<<PREP_BLOCKS, TB>>>(edge_raw, E, n, x0_src, x0_dst);

    for (int l = 0; l < 3; l++) {
        const float* xin = out + (size_t)(l + 1) * n * DD;
        float* xout      = out + (size_t)(l + 2) * n * DD;
        if (l > 0)
            k_gemm_mma<<<nb_gemm, 256, GEMM_SMEM>>>(xin, weights + (size_t)l * DD * DD, n);
        k_aggregate<<<nb_agg, TB>>>(biases + (size_t)l * DD, xout,
                                    (l == 2) ? out : nullptr,
                                    out + (size_t)n * DD, n);
    }
}

// round 14
// speedup vs baseline: 1.0584x; 1.0584x over previous
#include <cuda_runtime.h>
#include <cuda_bf16.h>
#include <cstdint>

// GCN: 3 layers, N=50000, E=600000, D=128.
// Out layout: [total | x0 | x1 | x2 | x3], each n*D f32.
// HMMA split-precision GEMM (BM=64, W pre-split); CSR aggregate; R11 prep.

#define DD 128
#define MAXN 50016
#define MAXE 600000
#define SCAN_B 512
#define LDT 136
#define BM 64

// Scratch (device globals; no allocation allowed)
__device__ float g_y[(size_t)MAXN * DD];
__device__ int   g_src[MAXE];
__device__ int   g_dst[MAXE];
__device__ int   g_off[MAXE];
__device__ int   g_csrc[MAXE];
__device__ float g_cw[MAXE];
__device__ float g_dinv[MAXN];
__device__ int   g_deg[MAXN];
__device__ int   g_rowstart[MAXN];
__device__ int   g_bsum[256];
__device__ int   g_is64;
__device__ __nv_bfloat16 g_wh[3][128 * LDT];   // W hi, padded rows
__device__ __nv_bfloat16 g_wl[3][128 * LDT];   // W lo

// ---------------------------------------------------------------------------
__device__ __forceinline__ uint32_t smem_u32(const void* p) {
    uint32_t a;
    asm("{ .reg .u64 t; cvta.to.shared.u64 t, %1; cvt.u32.u64 %0, t; }" : "=r"(a) : "l"(p));
    return a;
}
__device__ __forceinline__ void ldm_x4(uint32_t* r, uint32_t addr) {
    asm volatile("ldmatrix.sync.aligned.m8n8.x4.shared.b16 {%0,%1,%2,%3}, [%4];"
                 : "=r"(r[0]), "=r"(r[1]), "=r"(r[2]), "=r"(r[3]) : "r"(addr));
}
__device__ __forceinline__ void ldm_x4_t(uint32_t* r, uint32_t addr) {
    asm volatile("ldmatrix.sync.aligned.m8n8.x4.trans.shared.b16 {%0,%1,%2,%3}, [%4];"
                 : "=r"(r[0]), "=r"(r[1]), "=r"(r[2]), "=r"(r[3]) : "r"(addr));
}
__device__ __forceinline__ void mma_bf16(float* c, const uint32_t* a, const uint32_t* b) {
    asm volatile(
        "mma.sync.aligned.m16n8k16.row.col.f32.bf16.bf16.f32 "
        "{%0,%1,%2,%3}, {%4,%5,%6,%7}, {%8,%9}, {%0,%1,%2,%3};"
        : "+f"(c[0]), "+f"(c[1]), "+f"(c[2]), "+f"(c[3])
        : "r"(a[0]), "r"(a[1]), "r"(a[2]), "r"(a[3]), "r"(b[0]), "r"(b[1]));
}
__device__ __forceinline__ uint32_t bfbits(float v) {
    return (uint32_t)__bfloat16_as_ushort(__float2bfloat16(v));
}
__device__ __forceinline__ float bfval(uint32_t b) {
    return __bfloat162float(__ushort_as_bfloat16((unsigned short)b));
}

#define A_ELE (BM * LDT)          // 8704 bf16
#define B_ELE (128 * LDT)         // 17408 bf16
#define GEMM_SMEM ((2 * A_ELE + 2 * B_ELE) * 2)   // 104448 B -> 2 CTAs/SM

// ---------------------------------------------------------------------------
// Pre-split all layer weights into bf16 hi/lo padded tiles.
__global__ void k_wsplit(const float* __restrict__ W, int total) {
    int i = blockIdx.x * blockDim.x + threadIdx.x;
    if (i >= total) return;
    int l = i >> 14, rc = i & 16383;
    int r = rc >> 7, c = rc & 127;
    float v = W[i];
    uint32_t h = bfbits(v);
    g_wh[l][r * LDT + c] = __ushort_as_bfloat16((unsigned short)h);
    g_wl[l][r * LDT + c] = __float2bfloat16(v - bfval(h));
}

// ---------------------------------------------------------------------------
// GEMM: g_y = x @ W[layer].  BM=64 rows/CTA, 256 threads, 2 CTAs/SM.
// Warp w: rows (w&3)*16..+15, cols (w>>2)*64..+63.
__global__ __launch_bounds__(256) void k_gemm_mma(const float* __restrict__ x,
                                                  int layer, int n) {
    extern __shared__ __align__(16) char smem[];
    __nv_bfloat16* AH = (__nv_bfloat16*)smem;
    __nv_bfloat16* AL = AH + A_ELE;
    __nv_bfloat16* BH = AL + A_ELE;
    __nv_bfloat16* BL = BH + B_ELE;

    int tid = threadIdx.x;
    int wid = tid >> 5, lane = tid & 31;
    int row0 = blockIdx.x * BM;

    // Convert A tile (64 rows x 128 cols f32 -> bf16 hi/lo): 2048 float4s
#pragma unroll
    for (int i = 0; i < 8; i++) {
        int idx = tid + i * 256;
        int r = idx >> 5, f = idx & 31;
        int grow = row0 + r;
        float4 v = make_float4(0.f, 0.f, 0.f, 0.f);
        if (grow < n) v = *(const float4*)(x + (size_t)grow * DD + f * 4);
        uint32_t hx = bfbits(v.x), hy = bfbits(v.y), hz = bfbits(v.z), hw = bfbits(v.w);
        uint2 hh = make_uint2((hy << 16) | hx, (hw << 16) | hz);
        uint2 ll = make_uint2((bfbits(v.y - bfval(hy)) << 16) | bfbits(v.x - bfval(hx)),
                              (bfbits(v.w - bfval(hw)) << 16) | bfbits(v.z - bfval(hz)));
        *(uint2*)(AH + r * LDT + f * 4) = hh;
        *(uint2*)(AL + r * LDT + f * 4) = ll;
    }
    // Copy pre-split W tiles (raw bytes, no conversion): 2176 uint4 each
    {
        const uint4* wh4 = (const uint4*)g_wh[layer];
        const uint4* wl4 = (const uint4*)g_wl[layer];
        uint4* bh4 = (uint4*)BH;
        uint4* bl4 = (uint4*)BL;
#pragma unroll
        for (int i = 0; i < 9; i++) {
            int idx = tid + i * 256;
            if (idx < (B_ELE * 2) / 16) {
                bh4[idx] = wh4[idx];
                bl4[idx] = wl4[idx];
            }
        }
    }
    __syncthreads();

    int mrow  = (wid & 3) * 16;
    int nbase = (wid >> 2) * 64;
    uint32_t a_off_h = smem_u32(AH + (mrow + (lane & 15)) * LDT + (lane >> 4) * 8);
    uint32_t a_off_l = a_off_h + (uint32_t)(A_ELE * 2);

    float acc[8][4];
#pragma unroll
    for (int j = 0; j < 8; j++)
#pragma unroll
        for (int q = 0; q < 4; q++) acc[j][q] = 0.0f;

#pragma unroll
    for (int k = 0; k < 8; k++) {
        uint32_t ah[4], al[4];
        ldm_x4(ah, a_off_h + k * 32);
        ldm_x4(al, a_off_l + k * 32);
        uint32_t b_base = smem_u32(BH + (k * 16 + (lane & 15)) * LDT + nbase + (lane >> 4) * 8);
#pragma unroll
        for (int j2 = 0; j2 < 4; j2++) {
            uint32_t bh[4], bl[4];
            ldm_x4_t(bh, b_base + j2 * 32);
            ldm_x4_t(bl, b_base + j2 * 32 + (uint32_t)(B_ELE * 2));
            mma_bf16(acc[2 * j2],     ah, bh);
            mma_bf16(acc[2 * j2],     ah, bl);
            mma_bf16(acc[2 * j2],     al, bh);
            mma_bf16(acc[2 * j2 + 1], ah, bh + 2);
            mma_bf16(acc[2 * j2 + 1], ah, bl + 2);
            mma_bf16(acc[2 * j2 + 1], al, bh + 2);
        }
    }

    int r_lo = row0 + mrow + (lane >> 2);
    int r_hi = r_lo + 8;
    int cbase = (lane & 3) * 2;
#pragma unroll
    for (int j = 0; j < 8; j++) {
        int col = nbase + j * 8 + cbase;
        if (r_lo < n) *(float2*)(g_y + (size_t)r_lo * DD + col) = make_float2(acc[j][0], acc[j][1]);
        if (r_hi < n) *(float2*)(g_y + (size_t)r_hi * DD + col) = make_float2(acc[j][2], acc[j][3]);
    }
}

// ---------------------------------------------------------------------------
// Prep chain (R11, best measured).
__global__ void k_prep1(const unsigned int* __restrict__ raw, int n) {
    int i = blockIdx.x * blockDim.x + threadIdx.x;
    if (i < n) g_deg[i] = 0;
    if (i == 0) {
        int ok64 = (raw[1] == 0u) && (raw[3] == 0u) && (raw[5] == 0u) &&
                   (raw[7] == 0u) && (raw[9] == 0u) && (raw[11] == 0u);
        g_is64 = ok64 ? 1 : 0;
    }
}

__global__ void k_prep2(const void* __restrict__ raw, int E, int nb_e,
                        const float* __restrict__ emb, float* __restrict__ x0, int n) {
    int b = blockIdx.x;
    if (b < nb_e) {
        int e = b * blockDim.x + threadIdx.x;
        if (e >= E) return;
        int s, d;
        if (g_is64) {
            const long long* p = (const long long*)raw;
            s = (int)p[e]; d = (int)p[e + E];
        } else {
            const int* p = (const int*)raw;
            s = p[e]; d = p[e + E];
        }
        g_src[e] = s; g_dst[e] = d;
        g_off[e] = atomicAdd(&g_deg[d], 1);
    } else {
        int i = (b - nb_e) * blockDim.x + threadIdx.x;
        if (i < n * (DD / 4)) ((float4*)x0)[i] = ((const float4*)emb)[i];
    }
}

__global__ void k_scan1(int n) {
    __shared__ int sh[SCAN_B];
    int i = blockIdx.x * SCAN_B + threadIdx.x;
    int v = (i < n) ? g_deg[i] : 0;
    if (i < n) g_dinv[i] = rsqrtf((float)(v + 1));
    sh[threadIdx.x] = v;
    __syncthreads();
#pragma unroll
    for (int off = 1; off < SCAN_B; off <<= 1) {
        int t = (threadIdx.x >= off) ? sh[threadIdx.x - off] : 0;
        __syncthreads();
        sh[threadIdx.x] += t;
        __syncthreads();
    }
    if (i < n) g_rowstart[i] = sh[threadIdx.x] - v;
    if (threadIdx.x == SCAN_B - 1) g_bsum[blockIdx.x] = sh[SCAN_B - 1];
}

__global__ void k_scan3(int n) {
    __shared__ int s_off;
    int gb = blockIdx.x >> 1;
    if (threadIdx.x < 32) {
        int acc = 0;
        for (int b = threadIdx.x; b < gb; b += 32) acc += g_bsum[b];
#pragma unroll
        for (int o = 16; o; o >>= 1) acc += __shfl_xor_sync(0xFFFFFFFFu, acc, o);
        if (threadIdx.x == 0) s_off = acc;
    }
    __syncthreads();
    int i = blockIdx.x * blockDim.x + threadIdx.x;
    if (i < n) g_rowstart[i] += s_off;
}

__global__ void k_fill(int E) {
    int e = blockIdx.x * blockDim.x + threadIdx.x;
    if (e >= E) return;
    int s = g_src[e], d = g_dst[e];
    int pos = g_rowstart[d] + g_off[e];
    g_csrc[pos] = s;
    g_cw[pos]   = g_dinv[s];
}

// ---------------------------------------------------------------------------
// Aggregate (verified R11, unchanged).
__global__ __launch_bounds__(256) void k_aggregate(const float* __restrict__ bias,
                                                   float* __restrict__ xout,
                                                   float* __restrict__ total,
                                                   const float* __restrict__ xbase,
                                                   int n) {
    int t = blockIdx.x * blockDim.x + threadIdx.x;
    int node = t >> 5, lane = t & 31;
    if (node >= n) return;

    const float4* y4 = (const float4*)g_y;
    float ex = 0.f, ey = 0.f, ez = 0.f, ew = 0.f;

    int st  = g_rowstart[node];
    int cnt = g_deg[node];
    int k = 0;
    for (; k + 3 < cnt; k += 4) {
        int   s0 = g_csrc[st + k],     s1 = g_csrc[st + k + 1];
        int   s2 = g_csrc[st + k + 2], s3 = g_csrc[st + k + 3];
        float w0 = g_cw[st + k],       w1 = g_cw[st + k + 1];
        float w2 = g_cw[st + k + 2],   w3 = g_cw[st + k + 3];
        float4 v0 = __ldcg(y4 + (size_t)s0 * 32 + lane);
        float4 v1 = __ldcg(y4 + (size_t)s1 * 32 + lane);
        float4 v2 = __ldcg(y4 + (size_t)s2 * 32 + lane);
        float4 v3 = __ldcg(y4 + (size_t)s3 * 32 + lane);
        ex = fmaf(v0.x, w0, ex); ey = fmaf(v0.y, w0, ey);
        ez = fmaf(v0.z, w0, ez); ew = fmaf(v0.w, w0, ew);
        ex = fmaf(v1.x, w1, ex); ey = fmaf(v1.y, w1, ey);
        ez = fmaf(v1.z, w1, ez); ew = fmaf(v1.w, w1, ew);
        ex = fmaf(v2.x, w2, ex); ey = fmaf(v2.y, w2, ey);
        ez = fmaf(v2.z, w2, ez); ew = fmaf(v2.w, w2, ew);
        ex = fmaf(v3.x, w3, ex); ey = fmaf(v3.y, w3, ey);
        ez = fmaf(v3.z, w3, ez); ew = fmaf(v3.w, w3, ew);
    }
    for (; k < cnt; k++) {
        int   s0 = g_csrc[st + k];
        float w0 = g_cw[st + k];
        float4 v0 = __ldcg(y4 + (size_t)s0 * 32 + lane);
        ex = fmaf(v0.x, w0, ex); ey = fmaf(v0.y, w0, ey);
        ez = fmaf(v0.z, w0, ez); ew = fmaf(v0.w, w0, ew);
    }

    float s  = g_dinv[node];
    float s2 = s * s;
    float4 bb = ((const float4*)bias)[lane];
    float4 vs = y4[(size_t)node * 32 + lane];
    float ax = bb.x + fmaf(vs.x, s2, s * ex);
    float ay = bb.y + fmaf(vs.y, s2, s * ey);
    float az = bb.z + fmaf(vs.z, s2, s * ez);
    float aw = bb.w + fmaf(vs.w, s2, s * ew);

    size_t idx = (size_t)node * 32 + lane;
    ((float4*)xout)[idx] = make_float4(ax, ay, az, aw);

    if (total) {
        size_t nd4 = (size_t)n * 32;
        const float4* xb = (const float4*)xbase;
        float4 a = xb[idx], b2 = xb[nd4 + idx], c = xb[2 * nd4 + idx];
        ((float4*)total)[idx] = make_float4(a.x + b2.x + c.x + ax,
                                            a.y + b2.y + c.y + ay,
                                            a.z + b2.z + c.z + az,
                                            a.w + b2.w + c.w + aw);
    }
}

// ---------------------------------------------------------------------------
extern "C" void kernel_launch(void* const* d_in, const int* in_sizes, int n_in,
                              void* d_out, int out_size) {
    const float* item_emb = (const float*)d_in[0];
    const float* weights  = (const float*)d_in[1];
    const float* biases   = (const float*)d_in[2];
    const void*  edge_raw = d_in[3];

    int n = out_size / (5 * DD);
    int E = in_sizes[3] / 2;
    int emb_off = in_sizes[0] - n * DD;
    float* out = (float*)d_out;

    static bool attr_set = false;
    if (!attr_set) {
        cudaFuncSetAttribute(k_gemm_mma, cudaFuncAttributeMaxDynamicSharedMemorySize, GEMM_SMEM);
        attr_set = true;
    }

    const int TB = 256;
    int nb_n    = (n + TB - 1) / TB;
    int nb_e    = (E + TB - 1) / TB;
    int nb_nd4  = (n * 32 + TB - 1) / TB;
    int nb_scan = (n + SCAN_B - 1) / SCAN_B;
    int nb_gemm = (n + BM - 1) / BM;
    long long agg_threads = (long long)n * 32;
    int nb_agg = (int)((agg_threads + TB - 1) / TB);

    const float* x0_src = item_emb + emb_off;
    float* x0_dst = out + (size_t)n * DD;

    // Split W once, then GEMM_0 straight off item_emb.
    int wtotal = in_sizes[1];   // 3*128*128
    k_wsplit<<<(wtotal + TB - 1) / TB, TB>>>(weights, wtotal);
    k_gemm_mma<<<nb_gemm, 256, GEMM_SMEM>>>(x0_src, 0, n);

    // CSR build (+ x0 copy in prep2 tail blocks)
    k_prep1<<<nb_n, TB>>>((const unsigned int*)edge_raw, n);
    k_prep2<<<nb_e + nb_nd4, TB>>>(edge_raw, E, nb_e, x0_src, x0_dst, n);
    k_scan1<<<nb_scan, SCAN_B>>>(n);
    k_scan3<<<nb_n, TB>>>(n);
    k_fill<<<nb_e, TB>>>(E);

    for (int l = 0; l < 3; l++) {
        const float* xin = out + (size_t)(l + 1) * n * DD;
        float* xout      = out + (size_t)(l + 2) * n * DD;
        if (l > 0)
            k_gemm_mma<<<nb_gemm, 256, GEMM_SMEM>>>(xin, l, n);
        k_aggregate<<<nb_agg, TB>>>(biases + (size_t)l * DD, xout,
                                    (l == 2) ? out : nullptr,
                                    out + (size_t)n * DD, n);
    }
}

// round 15
// speedup vs baseline: 1.0912x; 1.0310x over previous
#include <cuda_runtime.h>
#include <cuda_bf16.h>
#include <cstdint>

// GCN: 3 layers, N=50000, E=600000, D=128.
// Out layout: [total | x0 | x1 | x2 | x3], each n*D f32.
// HMMA split-precision GEMM with W pre-arranged in mma fragment order
// (no B smem); CSR aggregate; R11 prep chain.

#define DD 128
#define MAXN 50016
#define MAXE 600000
#define SCAN_B 512
#define LDT 136
#define BM 64

// Scratch (device globals; no allocation allowed)
__device__ float g_y[(size_t)MAXN * DD];
__device__ int   g_src[MAXE];
__device__ int   g_dst[MAXE];
__device__ int   g_off[MAXE];
__device__ int   g_csrc[MAXE];
__device__ float g_cw[MAXE];
__device__ float g_dinv[MAXN];
__device__ int   g_deg[MAXN];
__device__ int   g_rowstart[MAXN];
__device__ int   g_bsum[256];
__device__ int   g_is64;
// W in mma-B-fragment order: [layer][kk 0..7][jj 0..15][lane 0..31]
// .x = hi(k0,k0+1)  .y = hi(k0+8,k0+9)  .z = lo(k0,k0+1)  .w = lo(k0+8,k0+9)
__device__ uint4 g_wfrag[3 * 8 * 16 * 32];

// ---------------------------------------------------------------------------
__device__ __forceinline__ uint32_t smem_u32(const void* p) {
    uint32_t a;
    asm("{ .reg .u64 t; cvta.to.shared.u64 t, %1; cvt.u32.u64 %0, t; }" : "=r"(a) : "l"(p));
    return a;
}
__device__ __forceinline__ void ldm_x4(uint32_t* r, uint32_t addr) {
    asm volatile("ldmatrix.sync.aligned.m8n8.x4.shared.b16 {%0,%1,%2,%3}, [%4];"
                 : "=r"(r[0]), "=r"(r[1]), "=r"(r[2]), "=r"(r[3]) : "r"(addr));
}
__device__ __forceinline__ void mma_bf16(float* c, const uint32_t* a, const uint32_t* b) {
    asm volatile(
        "mma.sync.aligned.m16n8k16.row.col.f32.bf16.bf16.f32 "
        "{%0,%1,%2,%3}, {%4,%5,%6,%7}, {%8,%9}, {%0,%1,%2,%3};"
        : "+f"(c[0]), "+f"(c[1]), "+f"(c[2]), "+f"(c[3])
        : "r"(a[0]), "r"(a[1]), "r"(a[2]), "r"(a[3]), "r"(b[0]), "r"(b[1]));
}
__device__ __forceinline__ uint32_t bfbits(float v) {
    return (uint32_t)__bfloat16_as_ushort(__float2bfloat16(v));
}
__device__ __forceinline__ float bfval(uint32_t b) {
    return __bfloat162float(__ushort_as_bfloat16((unsigned short)b));
}

#define A_ELE (BM * LDT)                 // 8704 bf16
#define GEMM_SMEM (2 * A_ELE * 2)        // AH+AL = 34816 B

// ---------------------------------------------------------------------------
// Pre-split W into bf16 hi/lo directly in mma B-fragment layout.
// One thread per (layer, kk, jj, lane).
__global__ void k_wsplit(const float* __restrict__ W, int total_frags) {
    int i = blockIdx.x * blockDim.x + threadIdx.x;
    if (i >= total_frags) return;
    int lane = i & 31;
    int jj   = (i >> 5) & 15;
    int kk   = (i >> 9) & 7;
    int l    = i >> 12;
    int n  = jj * 8 + (lane >> 2);
    int k0 = kk * 16 + (lane & 3) * 2;
    const float* Wl = W + (size_t)l * 16384;
    float v00 = Wl[(k0 + 0) * 128 + n];
    float v01 = Wl[(k0 + 1) * 128 + n];
    float v80 = Wl[(k0 + 8) * 128 + n];
    float v81 = Wl[(k0 + 9) * 128 + n];
    uint32_t h00 = bfbits(v00), h01 = bfbits(v01);
    uint32_t h80 = bfbits(v80), h81 = bfbits(v81);
    uint4 f;
    f.x = (h01 << 16) | h00;
    f.y = (h81 << 16) | h80;
    f.z = (bfbits(v01 - bfval(h01)) << 16) | bfbits(v00 - bfval(h00));
    f.w = (bfbits(v81 - bfval(h81)) << 16) | bfbits(v80 - bfval(h80));
    g_wfrag[i] = f;
}

// ---------------------------------------------------------------------------
// GEMM: g_y = x @ W[layer].  BM=64 rows/CTA, 256 threads.
// Warp w: rows (w&3)*16..+15, cols (w>>2)*64..+63.  B frags direct from gmem.
__global__ __launch_bounds__(256) void k_gemm_mma(const float* __restrict__ x,
                                                  int layer, int n) {
    extern __shared__ __align__(16) char smem[];
    __nv_bfloat16* AH = (__nv_bfloat16*)smem;
    __nv_bfloat16* AL = AH + A_ELE;

    int tid = threadIdx.x;
    int wid = tid >> 5, lane = tid & 31;
    int row0 = blockIdx.x * BM;

    // Convert A tile (64 rows x 128 cols f32 -> bf16 hi/lo): 2048 float4s
#pragma unroll
    for (int i = 0; i < 8; i++) {
        int idx = tid + i * 256;
        int r = idx >> 5, f = idx & 31;
        int grow = row0 + r;
        float4 v = make_float4(0.f, 0.f, 0.f, 0.f);
        if (grow < n) v = *(const float4*)(x + (size_t)grow * DD + f * 4);
        uint32_t hx = bfbits(v.x), hy = bfbits(v.y), hz = bfbits(v.z), hw = bfbits(v.w);
        uint2 hh = make_uint2((hy << 16) | hx, (hw << 16) | hz);
        uint2 ll = make_uint2((bfbits(v.y - bfval(hy)) << 16) | bfbits(v.x - bfval(hx)),
                              (bfbits(v.w - bfval(hw)) << 16) | bfbits(v.z - bfval(hz)));
        *(uint2*)(AH + r * LDT + f * 4) = hh;
        *(uint2*)(AL + r * LDT + f * 4) = ll;
    }
    __syncthreads();

    int mrow  = (wid & 3) * 16;
    int nbase = (wid >> 2) * 64;
    uint32_t a_off_h = smem_u32(AH + (mrow + (lane & 15)) * LDT + (lane >> 4) * 8);
    uint32_t a_off_l = a_off_h + (uint32_t)(A_ELE * 2);

    float acc[8][4];
#pragma unroll
    for (int j = 0; j < 8; j++)
#pragma unroll
        for (int q = 0; q < 4; q++) acc[j][q] = 0.0f;

    // Fragment base for this layer / this warp's n-range
    const uint4* fbase = g_wfrag + ((size_t)layer * 8 * 16 + (nbase >> 3)) * 32 + lane;

#pragma unroll
    for (int k = 0; k < 8; k++) {
        uint32_t ah[4], al[4];
        ldm_x4(ah, a_off_h + k * 32);
        ldm_x4(al, a_off_l + k * 32);
        const uint4* fk = fbase + (size_t)k * 16 * 32;
#pragma unroll
        for (int j2 = 0; j2 < 4; j2++) {
            uint4 f0 = fk[(2 * j2) * 32];
            uint4 f1 = fk[(2 * j2 + 1) * 32];
            uint32_t bh0[2] = {f0.x, f0.y}, bl0[2] = {f0.z, f0.w};
            uint32_t bh1[2] = {f1.x, f1.y}, bl1[2] = {f1.z, f1.w};
            mma_bf16(acc[2 * j2],     ah, bh0);
            mma_bf16(acc[2 * j2],     ah, bl0);
            mma_bf16(acc[2 * j2],     al, bh0);
            mma_bf16(acc[2 * j2 + 1], ah, bh1);
            mma_bf16(acc[2 * j2 + 1], ah, bl1);
            mma_bf16(acc[2 * j2 + 1], al, bh1);
        }
    }

    int r_lo = row0 + mrow + (lane >> 2);
    int r_hi = r_lo + 8;
    int cbase = (lane & 3) * 2;
#pragma unroll
    for (int j = 0; j < 8; j++) {
        int col = nbase + j * 8 + cbase;
        if (r_lo < n) *(float2*)(g_y + (size_t)r_lo * DD + col) = make_float2(acc[j][0], acc[j][1]);
        if (r_hi < n) *(float2*)(g_y + (size_t)r_hi * DD + col) = make_float2(acc[j][2], acc[j][3]);
    }
}

// ---------------------------------------------------------------------------
// Prep chain (R11, best measured).
__global__ void k_prep1(const unsigned int* __restrict__ raw, int n) {
    int i = blockIdx.x * blockDim.x + threadIdx.x;
    if (i < n) g_deg[i] = 0;
    if (i == 0) {
        int ok64 = (raw[1] == 0u) && (raw[3] == 0u) && (raw[5] == 0u) &&
                   (raw[7] == 0u) && (raw[9] == 0u) && (raw[11] == 0u);
        g_is64 = ok64 ? 1 : 0;
    }
}

__global__ void k_prep2(const void* __restrict__ raw, int E, int nb_e,
                        const float* __restrict__ emb, float* __restrict__ x0, int n) {
    int b = blockIdx.x;
    if (b < nb_e) {
        int e = b * blockDim.x + threadIdx.x;
        if (e >= E) return;
        int s, d;
        if (g_is64) {
            const long long* p = (const long long*)raw;
            s = (int)p[e]; d = (int)p[e + E];
        } else {
            const int* p = (const int*)raw;
            s = p[e]; d = p[e + E];
        }
        g_src[e] = s; g_dst[e] = d;
        g_off[e] = atomicAdd(&g_deg[d], 1);
    } else {
        int i = (b - nb_e) * blockDim.x + threadIdx.x;
        if (i < n * (DD / 4)) ((float4*)x0)[i] = ((const float4*)emb)[i];
    }
}

__global__ void k_scan1(int n) {
    __shared__ int sh[SCAN_B];
    int i = blockIdx.x * SCAN_B + threadIdx.x;
    int v = (i < n) ? g_deg[i] : 0;
    if (i < n) g_dinv[i] = rsqrtf((float)(v + 1));
    sh[threadIdx.x] = v;
    __syncthreads();
#pragma unroll
    for (int off = 1; off < SCAN_B; off <<= 1) {
        int t = (threadIdx.x >= off) ? sh[threadIdx.x - off] : 0;
        __syncthreads();
        sh[threadIdx.x] += t;
        __syncthreads();
    }
    if (i < n) g_rowstart[i] = sh[threadIdx.x] - v;
    if (threadIdx.x == SCAN_B - 1) g_bsum[blockIdx.x] = sh[SCAN_B - 1];
}

__global__ void k_scan3(int n) {
    __shared__ int s_off;
    int gb = blockIdx.x >> 1;
    if (threadIdx.x < 32) {
        int acc = 0;
        for (int b = threadIdx.x; b < gb; b += 32) acc += g_bsum[b];
#pragma unroll
        for (int o = 16; o; o >>= 1) acc += __shfl_xor_sync(0xFFFFFFFFu, acc, o);
        if (threadIdx.x == 0) s_off = acc;
    }
    __syncthreads();
    int i = blockIdx.x * blockDim.x + threadIdx.x;
    if (i < n) g_rowstart[i] += s_off;
}

__global__ void k_fill(int E) {
    int e = blockIdx.x * blockDim.x + threadIdx.x;
    if (e >= E) return;
    int s = g_src[e], d = g_dst[e];
    int pos = g_rowstart[d] + g_off[e];
    g_csrc[pos] = s;
    g_cw[pos]   = g_dinv[s];
}

// ---------------------------------------------------------------------------
// Aggregate (verified R11, unchanged).
__global__ __launch_bounds__(256) void k_aggregate(const float* __restrict__ bias,
                                                   float* __restrict__ xout,
                                                   float* __restrict__ total,
                                                   const float* __restrict__ xbase,
                                                   int n) {
    int t = blockIdx.x * blockDim.x + threadIdx.x;
    int node = t >> 5, lane = t & 31;
    if (node >= n) return;

    const float4* y4 = (const float4*)g_y;
    float ex = 0.f, ey = 0.f, ez = 0.f, ew = 0.f;

    int st  = g_rowstart[node];
    int cnt = g_deg[node];
    int k = 0;
    for (; k + 3 < cnt; k += 4) {
        int   s0 = g_csrc[st + k],     s1 = g_csrc[st + k + 1];
        int   s2 = g_csrc[st + k + 2], s3 = g_csrc[st + k + 3];
        float w0 = g_cw[st + k],       w1 = g_cw[st + k + 1];
        float w2 = g_cw[st + k + 2],   w3 = g_cw[st + k + 3];
        float4 v0 = __ldcg(y4 + (size_t)s0 * 32 + lane);
        float4 v1 = __ldcg(y4 + (size_t)s1 * 32 + lane);
        float4 v2 = __ldcg(y4 + (size_t)s2 * 32 + lane);
        float4 v3 = __ldcg(y4 + (size_t)s3 * 32 + lane);
        ex = fmaf(v0.x, w0, ex); ey = fmaf(v0.y, w0, ey);
        ez = fmaf(v0.z, w0, ez); ew = fmaf(v0.w, w0, ew);
        ex = fmaf(v1.x, w1, ex); ey = fmaf(v1.y, w1, ey);
        ez = fmaf(v1.z, w1, ez); ew = fmaf(v1.w, w1, ew);
        ex = fmaf(v2.x, w2, ex); ey = fmaf(v2.y, w2, ey);
        ez = fmaf(v2.z, w2, ez); ew = fmaf(v2.w, w2, ew);
        ex = fmaf(v3.x, w3, ex); ey = fmaf(v3.y, w3, ey);
        ez = fmaf(v3.z, w3, ez); ew = fmaf(v3.w, w3, ew);
    }
    for (; k < cnt; k++) {
        int   s0 = g_csrc[st + k];
        float w0 = g_cw[st + k];
        float4 v0 = __ldcg(y4 + (size_t)s0 * 32 + lane);
        ex = fmaf(v0.x, w0, ex); ey = fmaf(v0.y, w0, ey);
        ez = fmaf(v0.z, w0, ez); ew = fmaf(v0.w, w0, ew);
    }

    float s  = g_dinv[node];
    float s2 = s * s;
    float4 bb = ((const float4*)bias)[lane];
    float4 vs = y4[(size_t)node * 32 + lane];
    float ax = bb.x + fmaf(vs.x, s2, s * ex);
    float ay = bb.y + fmaf(vs.y, s2, s * ey);
    float az = bb.z + fmaf(vs.z, s2, s * ez);
    float aw = bb.w + fmaf(vs.w, s2, s * ew);

    size_t idx = (size_t)node * 32 + lane;
    ((float4*)xout)[idx] = make_float4(ax, ay, az, aw);

    if (total) {
        size_t nd4 = (size_t)n * 32;
        const float4* xb = (const float4*)xbase;
        float4 a = xb[idx], b2 = xb[nd4 + idx], c = xb[2 * nd4 + idx];
        ((float4*)total)[idx] = make_float4(a.x + b2.x + c.x + ax,
                                            a.y + b2.y + c.y + ay,
                                            a.z + b2.z + c.z + az,
                                            a.w + b2.w + c.w + aw);
    }
}

// ---------------------------------------------------------------------------
extern "C" void kernel_launch(void* const* d_in, const int* in_sizes, int n_in,
                              void* d_out, int out_size) {
    const float* item_emb = (const float*)d_in[0];
    const float* weights  = (const float*)d_in[1];
    const float* biases   = (const float*)d_in[2];
    const void*  edge_raw = d_in[3];

    int n = out_size / (5 * DD);
    int E = in_sizes[3] / 2;
    int emb_off = in_sizes[0] - n * DD;
    float* out = (float*)d_out;

    static bool attr_set = false;
    if (!attr_set) {
        cudaFuncSetAttribute(k_gemm_mma, cudaFuncAttributeMaxDynamicSharedMemorySize, GEMM_SMEM);
        attr_set = true;
    }

    const int TB = 256;
    int nb_n    = (n + TB - 1) / TB;
    int nb_e    = (E + TB - 1) / TB;
    int nb_nd4  = (n * 32 + TB - 1) / TB;
    int nb_scan = (n + SCAN_B - 1) / SCAN_B;
    int nb_gemm = (n + BM - 1) / BM;
    long long agg_threads = (long long)n * 32;
    int nb_agg = (int)((agg_threads + TB - 1) / TB);

    const float* x0_src = item_emb + emb_off;
    float* x0_dst = out + (size_t)n * DD;

    // Split W into fragment layout once, then GEMM_0 straight off item_emb.
    int nlayers = in_sizes[1] / (DD * DD);
    int total_frags = nlayers * 8 * 16 * 32;
    k_wsplit<<<(total_frags + TB - 1) / TB, TB>>>(weights, total_frags);
    k_gemm_mma<<<nb_gemm, 256, GEMM_SMEM>>>(x0_src, 0, n);

    // CSR build (+ x0 copy in prep2 tail blocks)
    k_prep1<<<nb_n, TB>>>((const unsigned int*)edge_raw, n);
    k_prep2<<<nb_e + nb_nd4, TB>>>(edge_raw, E, nb_e, x0_src, x0_dst, n);
    k_scan1<<<nb_scan, SCAN_B>>>(n);
    k_scan3<<<nb_n, TB>>>(n);
    k_fill<<<nb_e, TB>>>(E);

    for (int l = 0; l < 3; l++) {
        const float* xin = out + (size_t)(l + 1) * n * DD;
        float* xout      = out + (size_t)(l + 2) * n * DD;
        if (l > 0)
            k_gemm_mma<<<nb_gemm, 256, GEMM_SMEM>>>(xin, l, n);
        k_aggregate<<<nb_agg, TB>>>(biases + (size_t)l * DD, xout,
                                    (l == 2) ? out : nullptr,
                                    out + (size_t)n * DD, n);
    }
}